// round 14
// baseline (speedup 1.0000x reference)
#include <cuda_runtime.h>
#include <cuda_fp16.h>
#include <cstdint>

#define D 64
#define NODES_CAP 50000
#define EDGES_CAP 1600000
#define SCAN_BLK 1024

// ---------------- scratch (static device globals; no allocation) ----------------
__device__ int   g_counts[NODES_CAP];    // always zero between kernel_launch invocations
__device__ int   g_roff[NODES_CAP];      // partial prefix; after fill: +bsum = final roff[n+1]
__device__ int   g_bsum[64];
__device__ int   g_scan_done;            // always zero between invocations
__device__ float g_wsum[NODES_CAP];
__device__ int2  g_edge[EDGES_CAP];      // (src, float_as_int(w))
// double-buffered fp16 feature rows: layer i reads g_xh[i&1], writes g_xh[(i+1)&1]
__device__ __align__(128) __half2 g_xh[2][NODES_CAP * 32];

// ---------------- fused init (fp16 convert + hidden=x*t0) + degree histogram ----------------
__global__ void k_initcnt(const float* __restrict__ x, const float* __restrict__ temp,
                          const int* __restrict__ dst,
                          float* __restrict__ hidden, int nd2, int E) {
    int i = blockIdx.x * blockDim.x + threadIdx.x;
    if (i < nd2) {
        float t0 = __ldg(&temp[0]);
        float2 v = ((const float2*)x)[i];
        g_xh[0][i] = __floats2half2_rn(v.x, v.y);
        ((float2*)hidden)[i] = make_float2(v.x * t0, v.y * t0);
    }
    int e4 = i * 4;
    if (e4 + 4 <= E) {
        int4 d4 = __ldg((const int4*)&dst[e4]);
        atomicAdd(&g_counts[d4.x], 1);
        atomicAdd(&g_counts[d4.y], 1);
        atomicAdd(&g_counts[d4.z], 1);
        atomicAdd(&g_counts[d4.w], 1);
    } else {
        for (int e = e4; e < E; e++) atomicAdd(&g_counts[__ldg(&dst[e])], 1);
    }
}

// ---------------- scan1 + folded block-sum scan (last-block pattern) ----------------
// Self-cleaning: zeros g_counts after reading, resets g_scan_done -> no k_zero needed.
__global__ void k_scan1(int N, int nb) {
    __shared__ int s[SCAN_BLK];
    __shared__ int is_last;
    int tid = threadIdx.x;
    int i = blockIdx.x * SCAN_BLK + tid;
    int v = (i < N) ? g_counts[i] : 0;
    if (i < N) g_counts[i] = 0;              // restore pristine state for next replay
    s[tid] = v;
    __syncthreads();
    for (int off = 1; off < SCAN_BLK; off <<= 1) {
        int t = (tid >= off) ? s[tid - off] : 0;
        __syncthreads();
        s[tid] += t;
        __syncthreads();
    }
    if (i < N) g_roff[i] = s[tid] - v;          // block-local exclusive prefix
    if (tid == SCAN_BLK - 1) g_bsum[blockIdx.x] = s[tid];
    __threadfence();
    if (tid == 0) is_last = (atomicAdd(&g_scan_done, 1) == nb - 1);
    __syncthreads();
    if (is_last && tid < 32) {
        int lane = tid;
        int v0 = (lane < nb) ? g_bsum[lane] : 0;
        int v1 = (lane + 32 < nb) ? g_bsum[lane + 32] : 0;
        int s0 = v0;
        #pragma unroll
        for (int off = 1; off < 32; off <<= 1) {
            int t = __shfl_up_sync(0xffffffffu, s0, off);
            if (lane >= off) s0 += t;
        }
        int tot0 = __shfl_sync(0xffffffffu, s0, 31);
        int s1 = v1;
        #pragma unroll
        for (int off = 1; off < 32; off <<= 1) {
            int t = __shfl_up_sync(0xffffffffu, s1, off);
            if (lane >= off) s1 += t;
        }
        if (lane < nb) g_bsum[lane] = s0 - v0;                  // exclusive
        if (lane + 32 < nb) g_bsum[lane + 32] = tot0 + s1 - v1;
        if (lane == 0) g_scan_done = 0;      // restore pristine state
    }
}

// ---------------- CSR fill: bump partial roff directly, add block offset at use ----------------
// After this kernel: g_roff[n] + g_bsum[n>>10] == final_roff[n+1]
__global__ void k_fill(const int* __restrict__ src, const int* __restrict__ dst,
                       const float* __restrict__ w, int E) {
    int i = blockIdx.x * blockDim.x + threadIdx.x;
    int e4 = i * 4;
    if (e4 + 4 <= E) {
        int4   s4 = __ldg((const int4*)&src[e4]);
        int4   d4 = __ldg((const int4*)&dst[e4]);
        float4 w4 = __ldg((const float4*)&w[e4]);
        int p0 = atomicAdd(&g_roff[d4.x], 1) + g_bsum[d4.x >> 10];
        int p1 = atomicAdd(&g_roff[d4.y], 1) + g_bsum[d4.y >> 10];
        int p2 = atomicAdd(&g_roff[d4.z], 1) + g_bsum[d4.z >> 10];
        int p3 = atomicAdd(&g_roff[d4.w], 1) + g_bsum[d4.w >> 10];
        g_edge[p0] = make_int2(s4.x, __float_as_int(w4.x));
        g_edge[p1] = make_int2(s4.y, __float_as_int(w4.y));
        g_edge[p2] = make_int2(s4.z, __float_as_int(w4.z));
        g_edge[p3] = make_int2(s4.w, __float_as_int(w4.w));
    } else {
        for (int e = e4; e < E; e++) {
            int d = __ldg(&dst[e]);
            int p = atomicAdd(&g_roff[d], 1) + g_bsum[d >> 10];
            g_edge[p] = make_int2(__ldg(&src[e]), __float_as_int(__ldg(&w[e])));
        }
    }
}

// ---------------- fused per-layer kernel: SpMM (into smem) + tf32 MMA + epilogue ----------------
// Phase 1: each QUARTER-WARP owns one node (8 lanes x 16B = one 128B row line per gather);
// a warp walks its 8 nodes as 2 quads -> four independent edge streams in flight.
// Phase 2: MMA B-operands (W) loaded directly from global (L1-resident, shared by all
// blocks) -> no Ws smem tile, halves smem/block.
__device__ __forceinline__ uint32_t f2tf32(float f) {
    uint32_t r;
    asm("cvt.rna.tf32.f32 %0, %1;" : "=r"(r) : "f"(f));
    return r;
}

template <int STORE_WSUM>
__global__ void k_layer(const float* __restrict__ Wl, const float* __restrict__ bl,
                        const float* __restrict__ temp, int li, int write_xh,
                        float* __restrict__ hidden, int N) {
    __shared__ uint32_t As[64][68];   // As[node][d], tf32 bits
    int tid = threadIdx.x;
    int wid = tid >> 5, lane = tid & 31;
    int bn = blockIdx.x * 64;
    float t = __ldg(&temp[li + 1]);
    const __half2* __restrict__ xin = g_xh[li & 1];
    __half2* __restrict__ xout = g_xh[(li + 1) & 1];

    int quarter = lane >> 3;   // which node of the quad (0..3)
    int ql      = lane & 7;    // lane within quarter-warp; features 8*ql..8*ql+7

    // ---- Phase 1: SpMM, quarter-warp per node, 2 node-quads per warp ----
    #pragma unroll 1
    for (int k = 0; k < 2; k++) {
        int nloc = wid * 8 + k * 4 + quarter;
        int node = bn + nloc;
        float acc[8] = {};
        float ws = 0.f;
        int beg = 0, end = 0;
        if (node < N) {
            beg = (node == 0) ? 0 : (__ldg(&g_roff[node - 1]) + g_bsum[(node - 1) >> 10]);
            end = __ldg(&g_roff[node]) + g_bsum[node >> 10];
        }
        int cnt = end - beg;
        int m1 = max(cnt, __shfl_xor_sync(0xffffffffu, cnt, 8));
        int mxcnt = max(m1, __shfl_xor_sync(0xffffffffu, m1, 16));
        int e = beg;
        for (int it = 0; it < mxcnt; it += 8, e += 8) {
            int2 ed[8];
            uint4 v[8];
            #pragma unroll
            for (int j = 0; j < 8; j++)
                ed[j] = (e + j < end) ? __ldg(&g_edge[e + j]) : make_int2(0, 0);
            #pragma unroll
            for (int j = 0; j < 8; j++)
                v[j] = __ldg((const uint4*)(xin + ed[j].x * 32) + ql);
            #pragma unroll
            for (int j = 0; j < 8; j++) {
                float wt = __int_as_float(ed[j].y);     // 0.0f for padding
                if (STORE_WSUM) ws += wt;
                float2 f0 = __half22float2(*(__half2*)&v[j].x);
                float2 f1 = __half22float2(*(__half2*)&v[j].y);
                float2 f2 = __half22float2(*(__half2*)&v[j].z);
                float2 f3 = __half22float2(*(__half2*)&v[j].w);
                acc[0] = fmaf(f0.x, wt, acc[0]);
                acc[1] = fmaf(f0.y, wt, acc[1]);
                acc[2] = fmaf(f1.x, wt, acc[2]);
                acc[3] = fmaf(f1.y, wt, acc[3]);
                acc[4] = fmaf(f2.x, wt, acc[4]);
                acc[5] = fmaf(f2.y, wt, acc[5]);
                acc[6] = fmaf(f3.x, wt, acc[6]);
                acc[7] = fmaf(f3.y, wt, acc[7]);
            }
        }
        if (STORE_WSUM && ql == 0 && node < N) g_wsum[node] = ws;
        #pragma unroll
        for (int c = 0; c < 8; c++)
            As[nloc][8 * ql + c] = f2tf32(acc[c]);
    }
    __syncthreads();

    // ---- Phase 2: tf32 MMA, m16n32 per warp; B fragments from global (L1-hot) ----
    int g = lane >> 2, tg = lane & 3;
    int m0 = (wid & 3) * 16;
    int n0 = (wid >> 2) * 32;

    float acc[4][4] = {};
    #pragma unroll
    for (int k0 = 0; k0 < 64; k0 += 8) {
        uint32_t a0 = As[m0 + g][k0 + tg];
        uint32_t a1 = As[m0 + g + 8][k0 + tg];
        uint32_t a2 = As[m0 + g][k0 + tg + 4];
        uint32_t a3 = As[m0 + g + 8][k0 + tg + 4];
        #pragma unroll
        for (int j = 0; j < 4; j++) {
            const float* wrow = Wl + (n0 + j * 8 + g) * 64 + k0 + tg;
            uint32_t b0 = f2tf32(__ldg(wrow));
            uint32_t b1 = f2tf32(__ldg(wrow + 4));
            asm volatile(
                "mma.sync.aligned.m16n8k8.row.col.f32.tf32.tf32.f32 "
                "{%0,%1,%2,%3}, {%4,%5,%6,%7}, {%8,%9}, {%0,%1,%2,%3};"
                : "+f"(acc[j][0]), "+f"(acc[j][1]), "+f"(acc[j][2]), "+f"(acc[j][3])
                : "r"(a0), "r"(a1), "r"(a2), "r"(a3), "r"(b0), "r"(b1));
        }
    }

    // epilogue: thread holds rows (m0+g, m0+g+8), cols (2tg, 2tg+1) per n8-tile
    int node0 = bn + m0 + g;
    int node1 = node0 + 8;
    float ws0 = (node0 < N) ? g_wsum[node0] : 0.f;
    float ws1 = (node1 < N) ? g_wsum[node1] : 0.f;
    #pragma unroll
    for (int j = 0; j < 4; j++) {
        int o = n0 + j * 8 + 2 * tg;
        float b0 = __ldg(&bl[o]), b1 = __ldg(&bl[o + 1]);
        if (node0 < N) {
            float r0 = fmaxf(fmaf(b0, ws0, acc[j][0]), 0.f);
            float r1 = fmaxf(fmaf(b1, ws0, acc[j][1]), 0.f);
            if (write_xh) xout[node0 * 32 + (o >> 1)] = __floats2half2_rn(r0, r1);
            float2 h = *(float2*)&hidden[node0 * 64 + o];
            h.x = fmaf(r0, t, h.x);
            h.y = fmaf(r1, t, h.y);
            *(float2*)&hidden[node0 * 64 + o] = h;
        }
        if (node1 < N) {
            float r2 = fmaxf(fmaf(b0, ws1, acc[j][2]), 0.f);
            float r3 = fmaxf(fmaf(b1, ws1, acc[j][3]), 0.f);
            if (write_xh) xout[node1 * 32 + (o >> 1)] = __floats2half2_rn(r2, r3);
            float2 h = *(float2*)&hidden[node1 * 64 + o];
            h.x = fmaf(r2, t, h.x);
            h.y = fmaf(r3, t, h.y);
            *(float2*)&hidden[node1 * 64 + o] = h;
        }
    }
}

extern "C" void kernel_launch(void* const* d_in, const int* in_sizes, int n_in,
                              void* d_out, int out_size) {
    const float* x    = (const float*)d_in[0];
    const float* w    = (const float*)d_in[1];
    const float* W    = (const float*)d_in[2];
    const float* b    = (const float*)d_in[3];
    const float* temp = (const float*)d_in[4];
    const int*   src  = (const int*)d_in[5];
    const int*   dst  = (const int*)d_in[6];
    float* hidden = (float*)d_out;

    int nd = in_sizes[0];          // N * D
    int N  = nd / D;
    int E  = in_sizes[1];
    int L  = in_sizes[3] / D;
    int nd2 = nd / 2;

    int e4 = (E + 3) / 4;
    int mx = (e4 > nd2) ? e4 : nd2;
    k_initcnt<<<(mx + 255) / 256, 256>>>(x, temp, dst, hidden, nd2, E);
    int nb = (N + SCAN_BLK - 1) / SCAN_BLK;
    k_scan1<<<nb, SCAN_BLK>>>(N, nb);
    k_fill<<<(e4 + 255) / 256, 256>>>(src, dst, w, E);

    int layer_blocks = (N + 63) / 64;
    for (int i = 0; i < L; i++) {
        int write_xh = (i + 1 < L) ? 1 : 0;
        if (i == 0) k_layer<1><<<layer_blocks, 256>>>(W, b, temp, 0, write_xh, hidden, N);
        else        k_layer<0><<<layer_blocks, 256>>>(W + i * D * D, b + i * D, temp, i,
                                                      write_xh, hidden, N);
    }
}

// round 17
// speedup vs baseline: 1.2425x; 1.2425x over previous
#include <cuda_runtime.h>
#include <cuda_fp16.h>
#include <cstdint>

#define D 64
#define NODES_CAP 50000
#define EDGES_CAP 1600000
#define SCAN_BLK 1024

// ---------------- scratch (static device globals; no allocation) ----------------
__device__ int   g_counts[NODES_CAP];    // always zero between kernel_launch invocations
__device__ int   g_roff[NODES_CAP];      // partial prefix; after fill: +bsum = final roff[n+1]
__device__ int   g_bsum[64];
__device__ int   g_scan_done;            // always zero between invocations
__device__ float g_wsum[NODES_CAP];
__device__ int2  g_edge[EDGES_CAP];      // (src, float_as_int(w))
// double-buffered fp16 feature rows: layer i reads g_xh[i&1], writes g_xh[(i+1)&1]
__device__ __align__(128) __half2 g_xh[2][NODES_CAP * 32];

// ---------------- fused init (fp16 convert + hidden=x*t0) + degree histogram ----------------
__global__ void k_initcnt(const float* __restrict__ x, const float* __restrict__ temp,
                          const int* __restrict__ dst,
                          float* __restrict__ hidden, int nd2, int E) {
    int i = blockIdx.x * blockDim.x + threadIdx.x;
    if (i < nd2) {
        float t0 = __ldg(&temp[0]);
        float2 v = ((const float2*)x)[i];
        g_xh[0][i] = __floats2half2_rn(v.x, v.y);
        ((float2*)hidden)[i] = make_float2(v.x * t0, v.y * t0);
    }
    int e4 = i * 4;
    if (e4 + 4 <= E) {
        int4 d4 = __ldg((const int4*)&dst[e4]);
        atomicAdd(&g_counts[d4.x], 1);
        atomicAdd(&g_counts[d4.y], 1);
        atomicAdd(&g_counts[d4.z], 1);
        atomicAdd(&g_counts[d4.w], 1);
    } else {
        for (int e = e4; e < E; e++) atomicAdd(&g_counts[__ldg(&dst[e])], 1);
    }
}

// ---------------- scan1 + folded block-sum scan (last-block pattern) ----------------
// Self-cleaning: zeros g_counts after reading, resets g_scan_done -> no k_zero needed.
__global__ void k_scan1(int N, int nb) {
    __shared__ int s[SCAN_BLK];
    __shared__ int is_last;
    int tid = threadIdx.x;
    int i = blockIdx.x * SCAN_BLK + tid;
    int v = (i < N) ? g_counts[i] : 0;
    if (i < N) g_counts[i] = 0;              // restore pristine state for next replay
    s[tid] = v;
    __syncthreads();
    for (int off = 1; off < SCAN_BLK; off <<= 1) {
        int t = (tid >= off) ? s[tid - off] : 0;
        __syncthreads();
        s[tid] += t;
        __syncthreads();
    }
    if (i < N) g_roff[i] = s[tid] - v;          // block-local exclusive prefix
    if (tid == SCAN_BLK - 1) g_bsum[blockIdx.x] = s[tid];
    __threadfence();
    if (tid == 0) is_last = (atomicAdd(&g_scan_done, 1) == nb - 1);
    __syncthreads();
    if (is_last && tid < 32) {
        int lane = tid;
        int v0 = (lane < nb) ? g_bsum[lane] : 0;
        int v1 = (lane + 32 < nb) ? g_bsum[lane + 32] : 0;
        int s0 = v0;
        #pragma unroll
        for (int off = 1; off < 32; off <<= 1) {
            int t = __shfl_up_sync(0xffffffffu, s0, off);
            if (lane >= off) s0 += t;
        }
        int tot0 = __shfl_sync(0xffffffffu, s0, 31);
        int s1 = v1;
        #pragma unroll
        for (int off = 1; off < 32; off <<= 1) {
            int t = __shfl_up_sync(0xffffffffu, s1, off);
            if (lane >= off) s1 += t;
        }
        if (lane < nb) g_bsum[lane] = s0 - v0;                  // exclusive
        if (lane + 32 < nb) g_bsum[lane + 32] = tot0 + s1 - v1;
        if (lane == 0) g_scan_done = 0;      // restore pristine state
    }
}

// ---------------- CSR fill: bump partial roff directly, add block offset at use ----------------
// After this kernel: g_roff[n] + g_bsum[n>>10] == final_roff[n+1]
__global__ void k_fill(const int* __restrict__ src, const int* __restrict__ dst,
                       const float* __restrict__ w, int E) {
    int i = blockIdx.x * blockDim.x + threadIdx.x;
    int e4 = i * 4;
    if (e4 + 4 <= E) {
        int4   s4 = __ldg((const int4*)&src[e4]);
        int4   d4 = __ldg((const int4*)&dst[e4]);
        float4 w4 = __ldg((const float4*)&w[e4]);
        int p0 = atomicAdd(&g_roff[d4.x], 1) + g_bsum[d4.x >> 10];
        int p1 = atomicAdd(&g_roff[d4.y], 1) + g_bsum[d4.y >> 10];
        int p2 = atomicAdd(&g_roff[d4.z], 1) + g_bsum[d4.z >> 10];
        int p3 = atomicAdd(&g_roff[d4.w], 1) + g_bsum[d4.w >> 10];
        g_edge[p0] = make_int2(s4.x, __float_as_int(w4.x));
        g_edge[p1] = make_int2(s4.y, __float_as_int(w4.y));
        g_edge[p2] = make_int2(s4.z, __float_as_int(w4.z));
        g_edge[p3] = make_int2(s4.w, __float_as_int(w4.w));
    } else {
        for (int e = e4; e < E; e++) {
            int d = __ldg(&dst[e]);
            int p = atomicAdd(&g_roff[d], 1) + g_bsum[d >> 10];
            g_edge[p] = make_int2(__ldg(&src[e]), __float_as_int(__ldg(&w[e])));
        }
    }
}

// ---------------- fused per-layer kernel: SpMM (into smem) + tf32 MMA + epilogue ----------------
// Phase 1: each QUARTER-WARP owns one node (8 lanes x 16B = one 128B row line per gather);
// a warp walks its 8 nodes as 2 quads -> four independent edge streams in flight.
// Phase 2: W staged in smem (Ws tile) -- measured: W-from-global pushed the L1 pipe
// (56% busy on gathers) over the edge; smem is free since occupancy is register-bound.
__device__ __forceinline__ uint32_t f2tf32(float f) {
    uint32_t r;
    asm("cvt.rna.tf32.f32 %0, %1;" : "=r"(r) : "f"(f));
    return r;
}

template <int STORE_WSUM>
__global__ void k_layer(const float* __restrict__ Wl, const float* __restrict__ bl,
                        const float* __restrict__ temp, int li, int write_xh,
                        float* __restrict__ hidden, int N) {
    __shared__ uint32_t As[64][68];   // As[node][d], tf32 bits
    __shared__ uint32_t Ws[64][68];   // Ws[o][d], tf32 bits
    int tid = threadIdx.x;
    int wid = tid >> 5, lane = tid & 31;
    int bn = blockIdx.x * 64;
    float t = __ldg(&temp[li + 1]);
    const __half2* __restrict__ xin = g_xh[li & 1];
    __half2* __restrict__ xout = g_xh[(li + 1) & 1];

    for (int idx = tid; idx < 4096; idx += 256) {
        Ws[idx >> 6][idx & 63] = f2tf32(__ldg(&Wl[idx]));   // idx == o*64+d
    }

    int quarter = lane >> 3;   // which node of the quad (0..3)
    int ql      = lane & 7;    // lane within quarter-warp; features 8*ql..8*ql+7

    // ---- Phase 1: SpMM, quarter-warp per node, 2 node-quads per warp ----
    #pragma unroll 1
    for (int k = 0; k < 2; k++) {
        int nloc = wid * 8 + k * 4 + quarter;
        int node = bn + nloc;
        float acc[8] = {};
        float ws = 0.f;
        int beg = 0, end = 0;
        if (node < N) {
            beg = (node == 0) ? 0 : (__ldg(&g_roff[node - 1]) + g_bsum[(node - 1) >> 10]);
            end = __ldg(&g_roff[node]) + g_bsum[node >> 10];
        }
        int cnt = end - beg;
        int m1 = max(cnt, __shfl_xor_sync(0xffffffffu, cnt, 8));
        int mxcnt = max(m1, __shfl_xor_sync(0xffffffffu, m1, 16));
        int e = beg;
        for (int it = 0; it < mxcnt; it += 8, e += 8) {
            int2 ed[8];
            uint4 v[8];
            #pragma unroll
            for (int j = 0; j < 8; j++)
                ed[j] = (e + j < end) ? __ldg(&g_edge[e + j]) : make_int2(0, 0);
            #pragma unroll
            for (int j = 0; j < 8; j++)
                v[j] = __ldg((const uint4*)(xin + ed[j].x * 32) + ql);
            #pragma unroll
            for (int j = 0; j < 8; j++) {
                float wt = __int_as_float(ed[j].y);     // 0.0f for padding
                if (STORE_WSUM) ws += wt;
                float2 f0 = __half22float2(*(__half2*)&v[j].x);
                float2 f1 = __half22float2(*(__half2*)&v[j].y);
                float2 f2 = __half22float2(*(__half2*)&v[j].z);
                float2 f3 = __half22float2(*(__half2*)&v[j].w);
                acc[0] = fmaf(f0.x, wt, acc[0]);
                acc[1] = fmaf(f0.y, wt, acc[1]);
                acc[2] = fmaf(f1.x, wt, acc[2]);
                acc[3] = fmaf(f1.y, wt, acc[3]);
                acc[4] = fmaf(f2.x, wt, acc[4]);
                acc[5] = fmaf(f2.y, wt, acc[5]);
                acc[6] = fmaf(f3.x, wt, acc[6]);
                acc[7] = fmaf(f3.y, wt, acc[7]);
            }
        }
        if (STORE_WSUM && ql == 0 && node < N) g_wsum[node] = ws;
        #pragma unroll
        for (int c = 0; c < 8; c++)
            As[nloc][8 * ql + c] = f2tf32(acc[c]);
    }
    __syncthreads();

    // ---- Phase 2: tf32 MMA, m16n32 per warp ----
    int g = lane >> 2, tg = lane & 3;
    int m0 = (wid & 3) * 16;
    int n0 = (wid >> 2) * 32;

    float acc[4][4] = {};
    #pragma unroll
    for (int k0 = 0; k0 < 64; k0 += 8) {
        uint32_t a0 = As[m0 + g][k0 + tg];
        uint32_t a1 = As[m0 + g + 8][k0 + tg];
        uint32_t a2 = As[m0 + g][k0 + tg + 4];
        uint32_t a3 = As[m0 + g + 8][k0 + tg + 4];
        #pragma unroll
        for (int j = 0; j < 4; j++) {
            uint32_t b0 = Ws[n0 + j * 8 + g][k0 + tg];
            uint32_t b1 = Ws[n0 + j * 8 + g][k0 + tg + 4];
            asm volatile(
                "mma.sync.aligned.m16n8k8.row.col.f32.tf32.tf32.f32 "
                "{%0,%1,%2,%3}, {%4,%5,%6,%7}, {%8,%9}, {%0,%1,%2,%3};"
                : "+f"(acc[j][0]), "+f"(acc[j][1]), "+f"(acc[j][2]), "+f"(acc[j][3])
                : "r"(a0), "r"(a1), "r"(a2), "r"(a3), "r"(b0), "r"(b1));
        }
    }

    // epilogue: thread holds rows (m0+g, m0+g+8), cols (2tg, 2tg+1) per n8-tile
    int node0 = bn + m0 + g;
    int node1 = node0 + 8;
    float ws0 = (node0 < N) ? g_wsum[node0] : 0.f;
    float ws1 = (node1 < N) ? g_wsum[node1] : 0.f;
    #pragma unroll
    for (int j = 0; j < 4; j++) {
        int o = n0 + j * 8 + 2 * tg;
        float b0 = __ldg(&bl[o]), b1 = __ldg(&bl[o + 1]);
        if (node0 < N) {
            float r0 = fmaxf(fmaf(b0, ws0, acc[j][0]), 0.f);
            float r1 = fmaxf(fmaf(b1, ws0, acc[j][1]), 0.f);
            if (write_xh) xout[node0 * 32 + (o >> 1)] = __floats2half2_rn(r0, r1);
            float2 h = *(float2*)&hidden[node0 * 64 + o];
            h.x = fmaf(r0, t, h.x);
            h.y = fmaf(r1, t, h.y);
            *(float2*)&hidden[node0 * 64 + o] = h;
        }
        if (node1 < N) {
            float r2 = fmaxf(fmaf(b0, ws1, acc[j][2]), 0.f);
            float r3 = fmaxf(fmaf(b1, ws1, acc[j][3]), 0.f);
            if (write_xh) xout[node1 * 32 + (o >> 1)] = __floats2half2_rn(r2, r3);
            float2 h = *(float2*)&hidden[node1 * 64 + o];
            h.x = fmaf(r2, t, h.x);
            h.y = fmaf(r3, t, h.y);
            *(float2*)&hidden[node1 * 64 + o] = h;
        }
    }
}

extern "C" void kernel_launch(void* const* d_in, const int* in_sizes, int n_in,
                              void* d_out, int out_size) {
    const float* x    = (const float*)d_in[0];
    const float* w    = (const float*)d_in[1];
    const float* W    = (const float*)d_in[2];
    const float* b    = (const float*)d_in[3];
    const float* temp = (const float*)d_in[4];
    const int*   src  = (const int*)d_in[5];
    const int*   dst  = (const int*)d_in[6];
    float* hidden = (float*)d_out;

    int nd = in_sizes[0];          // N * D
    int N  = nd / D;
    int E  = in_sizes[1];
    int L  = in_sizes[3] / D;
    int nd2 = nd / 2;

    int e4 = (E + 3) / 4;
    int mx = (e4 > nd2) ? e4 : nd2;
    k_initcnt<<<(mx + 255) / 256, 256>>>(x, temp, dst, hidden, nd2, E);
    int nb = (N + SCAN_BLK - 1) / SCAN_BLK;
    k_scan1<<<nb, SCAN_BLK>>>(N, nb);
    k_fill<<<(e4 + 255) / 256, 256>>>(src, dst, w, E);

    int layer_blocks = (N + 63) / 64;
    for (int i = 0; i < L; i++) {
        int write_xh = (i + 1 < L) ? 1 : 0;
        if (i == 0) k_layer<1><<<layer_blocks, 256>>>(W, b, temp, 0, write_xh, hidden, N);
        else        k_layer<0><<<layer_blocks, 256>>>(W + i * D * D, b + i * D, temp, i,
                                                      write_xh, hidden, N);
    }
}